// round 11
// baseline (speedup 1.0000x reference)
#include <cuda_runtime.h>
#include <cuda_bf16.h>
#include <stdint.h>

// Scratch (no cudaMalloc allowed).
#define MAX_NODES 131072
__device__ unsigned char g_tbl4[MAX_NODES / 2];  // nibble-packed classes
__device__ double g_sum;
__device__ unsigned int g_count;

#define STAGE_EDGES 4096
#define STREAM_BYTES (STAGE_EDGES * 4)          // 16384 per stream
#define SLOT_BYTES (3 * STREAM_BYTES)           // 49152 per slot
#define N_SLOTS 3

// ---- mbarrier / TMA bulk helpers -----------------------------------------
#define MBAR_INIT(addr, cnt)                                                   \
    asm volatile("mbarrier.init.shared.b64 [%0], %1;" ::"r"(addr), "r"(cnt)    \
                 : "memory")
#define MBAR_EXPECT_TX(addr, tx)                                               \
    asm volatile("mbarrier.arrive.expect_tx.shared.b64 _, [%0], %1;" ::"r"(   \
                     addr),                                                    \
                 "r"(tx)                                                       \
                 : "memory")
#define TMA_BULK_G2S(dst, src, bytes, mbar)                                    \
    asm volatile(                                                              \
        "cp.async.bulk.shared::cluster.global.mbarrier::complete_tx::bytes "   \
        "[%0], [%1], %2, [%3];" ::"r"(dst),                                    \
        "l"(src), "r"(bytes), "r"(mbar)                                        \
        : "memory")
#define MBAR_WAIT_PARITY(addr, par)                                            \
    do {                                                                       \
        unsigned _done = 0;                                                    \
        while (!_done) {                                                       \
            asm volatile(                                                      \
                "{\n\t.reg .pred p;\n\t"                                       \
                "mbarrier.try_wait.parity.acquire.cta.shared::cta.b64 p, "     \
                "[%1], %2, 0x989680;\n\t"                                      \
                "selp.b32 %0, 1, 0, p;\n\t}"                                   \
                : "=r"(_done)                                                  \
                : "r"(addr), "r"(par)                                          \
                : "memory");                                                   \
        }                                                                      \
    } while (0)

// ---------------------------------------------------------------------------
// Kernel 1: nibble-pack classes; reset accumulator + counter.
// ---------------------------------------------------------------------------
__global__ void pack_kernel(const int* __restrict__ node_classes, int n_nodes) {
    int q = blockIdx.x * blockDim.x + threadIdx.x;
    if (q == 0) { g_sum = 0.0; g_count = 0u; }

    int base = q * 8;
    if (base + 8 <= n_nodes) {
        int4 a = *(const int4*)(node_classes + base);
        int4 b = *(const int4*)(node_classes + base + 4);
        unsigned w = (unsigned)(a.x & 15) | ((unsigned)(a.y & 15) << 4) |
                     ((unsigned)(a.z & 15) << 8) | ((unsigned)(a.w & 15) << 12) |
                     ((unsigned)(b.x & 15) << 16) | ((unsigned)(b.y & 15) << 20) |
                     ((unsigned)(b.z & 15) << 24) | ((unsigned)(b.w & 15) << 28);
        ((unsigned*)g_tbl4)[q] = w;
    } else if (base < n_nodes) {
        for (int i = base; i < n_nodes; i += 2) {
            unsigned lo = node_classes[i] & 15;
            unsigned hi = (i + 1 < n_nodes) ? (node_classes[i + 1] & 15) : 0u;
            g_tbl4[i >> 1] = (unsigned char)(lo | (hi << 4));
        }
    }
}

// ---------------------------------------------------------------------------
// Kernel 2: TMA-pipelined edge loop + fused finalize.
//   dyn smem: nibble table | bank-replicated masks | 3 x (src,dst,score) slots
// ---------------------------------------------------------------------------
__global__ void __launch_bounds__(1024, 1)
edge_loss_kernel(const float* __restrict__ edge_scores,
                 const int* __restrict__ edge_indices,
                 const float* __restrict__ adj,
                 float* __restrict__ out,
                 int n_edges, int n_nodes, int C) {
    extern __shared__ unsigned char smem[];
    int tbl_bytes = (n_nodes + 1) >> 1;
    int mask_off = (tbl_bytes + 127) & ~127;
    int buf_off = (mask_off + C * 32 * 4 + 1023) & ~1023;
    unsigned char* s_tbl4 = smem;
    unsigned int* s_mask = (unsigned int*)(smem + mask_off);

    __shared__ alignas(8) unsigned long long mbar[N_SLOTS];
    __shared__ float red[32];

    int tid = threadIdx.x;
    int nthreads = blockDim.x;
    int lane = tid & 31;
    unsigned smem_base = (unsigned)__cvta_generic_to_shared(smem);
    unsigned mbar_base = (unsigned)__cvta_generic_to_shared(mbar);

    // Stage nibble table (~50KB) into shared.
    {
        int n16 = tbl_bytes >> 4;
        const uint4* s16 = (const uint4*)g_tbl4;
        uint4* d16 = (uint4*)s_tbl4;
        for (int i = tid; i < n16; i += nthreads) d16[i] = s16[i];
        for (int i = (n16 << 4) + tid; i < tbl_bytes; i += nthreads)
            s_tbl4[i] = g_tbl4[i];
    }
    // Bank-replicated adjacency masks.
    if (tid < C * 32) {
        int cls = tid >> 5;
        unsigned m = 0;
        for (int j = 0; j < C; j++)
            m |= (adj[cls * C + j] != 0.0f ? 1u : 0u) << j;
        s_mask[tid] = m;
    }
    if (tid == 0) {
        #pragma unroll
        for (int k = 0; k < N_SLOTS; k++) MBAR_INIT(mbar_base + k * 8, 1);
    }
    asm volatile("fence.proxy.async.shared::cta;" ::: "memory");
    __syncthreads();

    const int* src_idx = edge_indices;
    const int* dst_idx = edge_indices + n_edges;
    int main_edges = n_edges & ~3;
    int n_stages = (main_edges + STAGE_EDGES - 1) / STAGE_EDGES;
    int grid = gridDim.x;
    int bid = blockIdx.x;
    int guard = n_nodes - 1;
    const float LN2 = 0.6931471805599453f;

    // Prologue: fill up to N_SLOTS stages.
    if (tid == 0) {
        #pragma unroll
        for (int k = 0; k < N_SLOTS; k++) {
            int g = bid + k * grid;
            if (g < n_stages) {
                int base = g * STAGE_EDGES;
                int count = min(STAGE_EDGES, main_edges - base);
                unsigned bytes = (unsigned)count * 4u;
                unsigned mb = mbar_base + k * 8;
                unsigned dst = smem_base + buf_off + k * SLOT_BYTES;
                MBAR_EXPECT_TX(mb, 3u * bytes);
                TMA_BULK_G2S(dst, src_idx + base, bytes, mb);
                TMA_BULK_G2S(dst + STREAM_BYTES, dst_idx + base, bytes, mb);
                TMA_BULK_G2S(dst + 2 * STREAM_BYTES, edge_scores + base, bytes, mb);
            }
        }
    }

    float acc = 0.0f;
    int phase[N_SLOTS] = {0, 0, 0};
    int slot = 0;
    for (int g = bid; g < n_stages; g += grid) {
        MBAR_WAIT_PARITY(mbar_base + slot * 8, phase[slot]);
        phase[slot] ^= 1;

        int base = g * STAGE_EDGES;
        int count = min(STAGE_EDGES, main_edges - base);
        unsigned char* buf = smem + buf_off + slot * SLOT_BYTES;

        if (tid * 4 < count) {
            uint4 s4 = ((const uint4*)buf)[tid];
            uint4 d4 = ((const uint4*)(buf + STREAM_BYTES))[tid];
            float4 sc = ((const float4*)(buf + 2 * STREAM_BYTES))[tid];

            int si[4] = {(int)s4.x, (int)s4.y, (int)s4.z, (int)s4.w};
            int di[4] = {(int)d4.x, (int)d4.y, (int)d4.z, (int)d4.w};
            float sv[4] = {sc.x, sc.y, sc.z, sc.w};
            #pragma unroll
            for (int k = 0; k < 4; k++) {
                int ia = min(si[k], guard);
                int ib = min(di[k], guard);
                unsigned a = (s_tbl4[ia >> 1] >> ((ia & 1) << 2)) & 15u;
                unsigned b = (s_tbl4[ib >> 1] >> ((ib & 1) << 2)) & 15u;
                unsigned y = (s_mask[(a << 5) | lane] >> b) & 1u;
                float v = sv[k];
                float e = __expf(-fabsf(v));
                acc += fmaxf(v, 0.0f) - (y ? v : 0.0f) +
                       LN2 * __log2f(1.0f + e);
            }
        }
        __syncthreads();  // all threads done with this slot before refill

        if (tid == 0) {
            int gn = g + N_SLOTS * grid;
            if (gn < n_stages) {
                int nbase = gn * STAGE_EDGES;
                int ncount = min(STAGE_EDGES, main_edges - nbase);
                unsigned bytes = (unsigned)ncount * 4u;
                unsigned mb = mbar_base + slot * 8;
                unsigned dst = smem_base + buf_off + slot * SLOT_BYTES;
                MBAR_EXPECT_TX(mb, 3u * bytes);
                TMA_BULK_G2S(dst, src_idx + nbase, bytes, mb);
                TMA_BULK_G2S(dst + STREAM_BYTES, dst_idx + nbase, bytes, mb);
                TMA_BULK_G2S(dst + 2 * STREAM_BYTES, edge_scores + nbase, bytes, mb);
            }
        }
        slot = (slot == N_SLOTS - 1) ? 0 : slot + 1;
    }

    // Residual edges (n_edges % 4) by one thread via direct loads.
    if (bid == 0 && tid == 0) {
        for (int e = main_edges; e < n_edges; e++) {
            int ia = min(src_idx[e], guard);
            int ib = min(dst_idx[e], guard);
            unsigned a = (s_tbl4[ia >> 1] >> ((ia & 1) << 2)) & 15u;
            unsigned b = (s_tbl4[ib >> 1] >> ((ib & 1) << 2)) & 15u;
            unsigned y = (s_mask[(a << 5)] >> b) & 1u;
            float v = edge_scores[e];
            acc += fmaxf(v, 0.0f) - (y ? v : 0.0f) +
                   LN2 * __log2f(1.0f + __expf(-fabsf(v)));
        }
    }

    // Block reduction -> one double atomic per block; last block writes mean.
    int wid = tid >> 5;
    #pragma unroll
    for (int off = 16; off > 0; off >>= 1)
        acc += __shfl_xor_sync(0xFFFFFFFFu, acc, off);
    if (lane == 0) red[wid] = acc;
    __syncthreads();
    if (wid == 0) {
        float v = (lane < (nthreads >> 5)) ? red[lane] : 0.0f;
        #pragma unroll
        for (int off = 16; off > 0; off >>= 1)
            v += __shfl_xor_sync(0xFFFFFFFFu, v, off);
        if (lane == 0) {
            atomicAdd(&g_sum, (double)v);
            __threadfence();
            unsigned done = atomicAdd(&g_count, 1u);
            if (done == gridDim.x - 1) {
                double total = *((volatile double*)&g_sum);
                out[0] = (float)(total / (double)n_edges);
            }
        }
    }
}

extern "C" void kernel_launch(void* const* d_in, const int* in_sizes, int n_in,
                              void* d_out, int out_size) {
    const int* node_classes = (const int*)d_in[0];
    const float* edge_scores = (const float*)d_in[1];
    const int* edge_indices = (const int*)d_in[2];
    const float* adj = (const float*)d_in[3];

    int n_nodes = in_sizes[0];
    int n_edges = in_sizes[1];
    int C = 1;
    while (C * C < in_sizes[3]) C++;  // 144 -> 12

    int tbl_bytes = (n_nodes + 1) >> 1;
    int mask_off = (tbl_bytes + 127) & ~127;
    int buf_off = (mask_off + C * 32 * 4 + 1023) & ~1023;
    size_t smem_bytes = (size_t)buf_off + (size_t)N_SLOTS * SLOT_BYTES;

    cudaFuncSetAttribute(edge_loss_kernel,
                         cudaFuncAttributeMaxDynamicSharedMemorySize,
                         (int)smem_bytes);

    int nsm = 148;
    cudaDeviceGetAttribute(&nsm, cudaDevAttrMultiProcessorCount, 0);

    int pack_threads = 256;
    int pack_blocks = ((n_nodes + 7) / 8 + pack_threads - 1) / pack_threads;
    pack_kernel<<<pack_blocks, pack_threads>>>(node_classes, n_nodes);

    edge_loss_kernel<<<nsm, 1024, smem_bytes>>>(edge_scores, edge_indices,
                                                adj, (float*)d_out,
                                                n_edges, n_nodes, C);
}

// round 12
// speedup vs baseline: 1.2008x; 1.2008x over previous
#include <cuda_runtime.h>
#include <cuda_bf16.h>
#include <stdint.h>

// Scratch (no cudaMalloc allowed).
#define MAX_NODES 131072
__device__ unsigned char g_cls[MAX_NODES];  // per-node class (0..C-1)
__device__ double g_sum;
__device__ unsigned int g_count;

// Policy-hinted 16B stream load: L2::evict_last via createpolicy descriptor.
// Pins the (96MB < 126MB L2) streams across graph replays.
#define LDG_POL_V4(v0, v1, v2, v3, p, pol)                                     \
    asm volatile(                                                              \
        "ld.global.nc.L2::cache_hint.v4.b32 {%0,%1,%2,%3}, [%4], %5;"          \
        : "=r"(v0), "=r"(v1), "=r"(v2), "=r"(v3)                               \
        : "l"(p), "l"(pol))

// ---------------------------------------------------------------------------
// Kernel 1: pack int32 classes -> uint8 table; reset accumulator + counter.
// ---------------------------------------------------------------------------
__global__ void pack_kernel(const int* __restrict__ node_classes, int n_nodes) {
    int q = blockIdx.x * blockDim.x + threadIdx.x;
    if (q == 0) { g_sum = 0.0; g_count = 0u; }

    int base = q * 8;
    if (base + 8 <= n_nodes) {
        int4 a = *(const int4*)(node_classes + base);
        int4 b = *(const int4*)(node_classes + base + 4);
        unsigned long long w =
            (unsigned long long)(unsigned char)a.x |
            ((unsigned long long)(unsigned char)a.y << 8) |
            ((unsigned long long)(unsigned char)a.z << 16) |
            ((unsigned long long)(unsigned char)a.w << 24) |
            ((unsigned long long)(unsigned char)b.x << 32) |
            ((unsigned long long)(unsigned char)b.y << 40) |
            ((unsigned long long)(unsigned char)b.z << 48) |
            ((unsigned long long)(unsigned char)b.w << 56);
        *(unsigned long long*)(g_cls + base) = w;
    } else if (base < n_nodes) {
        for (int i = base; i < n_nodes; i++)
            g_cls[i] = (unsigned char)node_classes[i];
    }
}

// ---------------------------------------------------------------------------
// Kernel 2: main edge loop + fused finalize.
//   dyn smem: [0, n_nodes) uint8 class table, then (128B aligned)
//             C*32 uint bank-replicated adjacency masks.
// ---------------------------------------------------------------------------
__global__ void __launch_bounds__(768, 2)
edge_loss_kernel(const float* __restrict__ edge_scores,
                 const int* __restrict__ edge_indices,
                 const float* __restrict__ adj,
                 float* __restrict__ out,
                 int n_edges, int n_nodes, int C) {
    extern __shared__ unsigned char smem[];
    unsigned char* s_tbl = smem;
    int mask_off = (n_nodes + 127) & ~127;
    unsigned int* s_mask = (unsigned int*)(smem + mask_off);

    int tid = threadIdx.x;
    int nthreads = blockDim.x;
    int lane = tid & 31;

    // L2 evict_last policy descriptor (fraction 1.0).
    unsigned long long pol;
    asm("createpolicy.fractional.L2::evict_last.b64 %0, 1.0;" : "=l"(pol));

    // Stage class table into shared.
    int n16 = n_nodes >> 4;
    const uint4* src16 = (const uint4*)g_cls;
    uint4* dst16 = (uint4*)s_tbl;
    for (int i = tid; i < n16; i += nthreads) dst16[i] = src16[i];
    for (int i = (n16 << 4) + tid; i < n_nodes; i += nthreads) s_tbl[i] = g_cls[i];

    // Bank-replicated adjacency masks: s_mask[cls*32 + lane] == mask[cls].
    if (tid < C * 32) {
        int cls = tid >> 5;
        unsigned int m = 0;
        for (int j = 0; j < C; j++)
            m |= (adj[cls * C + j] != 0.0f ? 1u : 0u) << j;
        s_mask[tid] = m;
    }
    __syncthreads();

    const int* src_idx = edge_indices;            // row 0
    const int* dst_idx = edge_indices + n_edges;  // row 1

    int nq = n_edges >> 2;  // groups of 4 edges per thread-iter
    int gtid = blockIdx.x * nthreads + tid;
    int gstride = gridDim.x * nthreads;
    int guard = n_nodes - 1;
    const float LN2 = 0.6931471805599453f;

    float acc = 0.0f;

    #pragma unroll 2
    for (int q = gtid; q < nq; q += gstride) {
        int s0i, s1i, s2i, s3i, d0i, d1i, d2i, d3i;
        unsigned c0, c1, c2, c3;
        LDG_POL_V4(s0i, s1i, s2i, s3i, src_idx + 4 * q, pol);
        LDG_POL_V4(d0i, d1i, d2i, d3i, dst_idx + 4 * q, pol);
        LDG_POL_V4(c0, c1, c2, c3, edge_scores + 4 * q, pol);

        unsigned a0 = s_tbl[min(s0i, guard)];
        unsigned b0 = s_tbl[min(d0i, guard)];
        unsigned a1 = s_tbl[min(s1i, guard)];
        unsigned b1 = s_tbl[min(d1i, guard)];
        unsigned a2 = s_tbl[min(s2i, guard)];
        unsigned b2 = s_tbl[min(d2i, guard)];
        unsigned a3 = s_tbl[min(s3i, guard)];
        unsigned b3 = s_tbl[min(d3i, guard)];

        unsigned y0 = (s_mask[(a0 << 5) | lane] >> b0) & 1u;
        unsigned y1 = (s_mask[(a1 << 5) | lane] >> b1) & 1u;
        unsigned y2 = (s_mask[(a2 << 5) | lane] >> b2) & 1u;
        unsigned y3 = (s_mask[(a3 << 5) | lane] >> b3) & 1u;

        float s0 = __uint_as_float(c0), s1 = __uint_as_float(c1);
        float s2 = __uint_as_float(c2), s3 = __uint_as_float(c3);
        // per_edge = max(s,0) - s*y + log(1 + exp(-|s|))
        float e0 = __expf(-fabsf(s0));
        float e1 = __expf(-fabsf(s1));
        float e2 = __expf(-fabsf(s2));
        float e3 = __expf(-fabsf(s3));
        acc += fmaxf(s0, 0.0f) - (y0 ? s0 : 0.0f) + LN2 * __log2f(1.0f + e0);
        acc += fmaxf(s1, 0.0f) - (y1 ? s1 : 0.0f) + LN2 * __log2f(1.0f + e1);
        acc += fmaxf(s2, 0.0f) - (y2 ? s2 : 0.0f) + LN2 * __log2f(1.0f + e2);
        acc += fmaxf(s3, 0.0f) - (y3 ? s3 : 0.0f) + LN2 * __log2f(1.0f + e3);
    }

    // Tail edges (n_edges % 4).
    if (gtid == 0) {
        for (int e = nq << 2; e < n_edges; e++) {
            unsigned a = s_tbl[min(src_idx[e], guard)];
            unsigned b = s_tbl[min(dst_idx[e], guard)];
            unsigned y = (s_mask[(a << 5) | lane] >> b) & 1u;
            float s = edge_scores[e];
            acc += fmaxf(s, 0.0f) - (y ? s : 0.0f) +
                   LN2 * __log2f(1.0f + __expf(-fabsf(s)));
        }
    }

    // Block reduction: warp shuffle -> shared -> one double atomic per block.
    __shared__ float red[32];
    int wid = tid >> 5;
    #pragma unroll
    for (int off = 16; off > 0; off >>= 1)
        acc += __shfl_xor_sync(0xFFFFFFFFu, acc, off);
    if (lane == 0) red[wid] = acc;
    __syncthreads();
    if (wid == 0) {
        int nw = nthreads >> 5;
        float v = (lane < nw) ? red[lane] : 0.0f;
        #pragma unroll
        for (int off = 16; off > 0; off >>= 1)
            v += __shfl_xor_sync(0xFFFFFFFFu, v, off);
        if (lane == 0) {
            atomicAdd(&g_sum, (double)v);
            __threadfence();
            unsigned done = atomicAdd(&g_count, 1u);
            if (done == gridDim.x - 1) {
                double total = *((volatile double*)&g_sum);
                out[0] = (float)(total / (double)n_edges);
            }
        }
    }
}

extern "C" void kernel_launch(void* const* d_in, const int* in_sizes, int n_in,
                              void* d_out, int out_size) {
    // Inputs: node_classes(int32), edge_scores(f32), edge_indices(int32, 2xN),
    // valid_adjacency(f32, CxC).
    const int* node_classes = (const int*)d_in[0];
    const float* edge_scores = (const float*)d_in[1];
    const int* edge_indices = (const int*)d_in[2];
    const float* adj = (const float*)d_in[3];

    int n_nodes = in_sizes[0];
    int n_edges = in_sizes[1];
    int C = 1;
    while (C * C < in_sizes[3]) C++;  // 144 -> 12

    int mask_off = (n_nodes + 127) & ~127;
    size_t smem_bytes = (size_t)mask_off + (size_t)C * 32 * sizeof(unsigned int);

    cudaFuncSetAttribute(edge_loss_kernel,
                         cudaFuncAttributeMaxDynamicSharedMemorySize,
                         (int)smem_bytes);

    int nsm = 148;
    cudaDeviceGetAttribute(&nsm, cudaDevAttrMultiProcessorCount, 0);

    int pack_threads = 256;
    int pack_blocks = ((n_nodes + 7) / 8 + pack_threads - 1) / pack_threads;
    pack_kernel<<<pack_blocks, pack_threads>>>(node_classes, n_nodes);

    // 2 CTAs per SM (smem ~99.3KB each), 768 threads -> 48 warps/SM.
    edge_loss_kernel<<<2 * nsm, 768, smem_bytes>>>(edge_scores, edge_indices,
                                                   adj, (float*)d_out,
                                                   n_edges, n_nodes, C);
}

// round 13
// speedup vs baseline: 1.2962x; 1.0794x over previous
#include <cuda_runtime.h>
#include <cuda_bf16.h>
#include <stdint.h>

// Scratch (no cudaMalloc allowed).
#define MAX_NODES 131072
__device__ unsigned char g_tbl4[MAX_NODES / 2];  // nibble-packed classes
__device__ double g_sum;
__device__ unsigned int g_count;

// ---------------------------------------------------------------------------
// Kernel 1: nibble-pack classes (2 nodes/thread, max parallelism);
// reset accumulator + completion counter.
// ---------------------------------------------------------------------------
__global__ void pack_kernel(const int* __restrict__ node_classes, int n_nodes) {
    int q = blockIdx.x * blockDim.x + threadIdx.x;
    if (q == 0) { g_sum = 0.0; g_count = 0u; }

    int base = q * 2;
    if (base + 2 <= n_nodes) {
        int2 c = *(const int2*)(node_classes + base);
        g_tbl4[q] = (unsigned char)((c.x & 15) | ((c.y & 15) << 4));
    } else if (base < n_nodes) {
        g_tbl4[q] = (unsigned char)(node_classes[base] & 15);
    }
}

// ---------------------------------------------------------------------------
// Kernel 2: main edge loop + fused finalize.
//   dyn smem: [0, ceil(n_nodes/2)) nibble table, then (128B aligned)
//             C*32 uint bank-replicated adjacency masks.
// ---------------------------------------------------------------------------
__global__ void __launch_bounds__(768, 2)
edge_loss_kernel(const float* __restrict__ edge_scores,
                 const int* __restrict__ edge_indices,
                 const float* __restrict__ adj,
                 float* __restrict__ out,
                 int n_edges, int n_nodes, int C) {
    extern __shared__ unsigned char smem[];
    unsigned char* s_tbl4 = smem;
    int tbl_bytes = (n_nodes + 1) >> 1;
    int mask_off = (tbl_bytes + 127) & ~127;
    unsigned int* s_mask = (unsigned int*)(smem + mask_off);

    int tid = threadIdx.x;
    int nthreads = blockDim.x;
    int lane = tid & 31;

    // Stage nibble table (~50KB) into shared.
    {
        int n16 = tbl_bytes >> 4;
        const uint4* s16 = (const uint4*)g_tbl4;
        uint4* d16 = (uint4*)s_tbl4;
        for (int i = tid; i < n16; i += nthreads) d16[i] = s16[i];
        for (int i = (n16 << 4) + tid; i < tbl_bytes; i += nthreads)
            s_tbl4[i] = g_tbl4[i];
    }
    // Bank-replicated adjacency masks: s_mask[cls*32 + lane] == mask[cls].
    if (tid < C * 32) {
        int cls = tid >> 5;
        unsigned int m = 0;
        for (int j = 0; j < C; j++)
            m |= (adj[cls * C + j] != 0.0f ? 1u : 0u) << j;
        s_mask[tid] = m;
    }
    __syncthreads();

    const int* src_idx = edge_indices;            // row 0
    const int* dst_idx = edge_indices + n_edges;  // row 1

    int nq = n_edges >> 2;  // groups of 4 edges per thread-iter
    int gtid = blockIdx.x * nthreads + tid;
    int gstride = gridDim.x * nthreads;
    int guard = n_nodes - 1;
    const float LN2 = 0.6931471805599453f;

    float acc = 0.0f;

    #pragma unroll 2
    for (int q = gtid; q < nq; q += gstride) {
        int4 s4 = *(const int4*)(src_idx + 4 * q);
        int4 d4 = *(const int4*)(dst_idx + 4 * q);
        float4 sc = *(const float4*)(edge_scores + 4 * q);

        int ia0 = min(s4.x, guard), ib0 = min(d4.x, guard);
        int ia1 = min(s4.y, guard), ib1 = min(d4.y, guard);
        int ia2 = min(s4.z, guard), ib2 = min(d4.z, guard);
        int ia3 = min(s4.w, guard), ib3 = min(d4.w, guard);

        unsigned a0 = (s_tbl4[ia0 >> 1] >> ((ia0 & 1) << 2)) & 15u;
        unsigned b0 = (s_tbl4[ib0 >> 1] >> ((ib0 & 1) << 2)) & 15u;
        unsigned a1 = (s_tbl4[ia1 >> 1] >> ((ia1 & 1) << 2)) & 15u;
        unsigned b1 = (s_tbl4[ib1 >> 1] >> ((ib1 & 1) << 2)) & 15u;
        unsigned a2 = (s_tbl4[ia2 >> 1] >> ((ia2 & 1) << 2)) & 15u;
        unsigned b2 = (s_tbl4[ib2 >> 1] >> ((ib2 & 1) << 2)) & 15u;
        unsigned a3 = (s_tbl4[ia3 >> 1] >> ((ia3 & 1) << 2)) & 15u;
        unsigned b3 = (s_tbl4[ib3 >> 1] >> ((ib3 & 1) << 2)) & 15u;

        unsigned y0 = (s_mask[(a0 << 5) | lane] >> b0) & 1u;
        unsigned y1 = (s_mask[(a1 << 5) | lane] >> b1) & 1u;
        unsigned y2 = (s_mask[(a2 << 5) | lane] >> b2) & 1u;
        unsigned y3 = (s_mask[(a3 << 5) | lane] >> b3) & 1u;

        float s0 = sc.x, s1 = sc.y, s2 = sc.z, s3 = sc.w;
        // per_edge = max(s,0) - s*y + log(1 + exp(-|s|))
        float e0 = __expf(-fabsf(s0));
        float e1 = __expf(-fabsf(s1));
        float e2 = __expf(-fabsf(s2));
        float e3 = __expf(-fabsf(s3));
        acc += fmaxf(s0, 0.0f) - (y0 ? s0 : 0.0f) + LN2 * __log2f(1.0f + e0);
        acc += fmaxf(s1, 0.0f) - (y1 ? s1 : 0.0f) + LN2 * __log2f(1.0f + e1);
        acc += fmaxf(s2, 0.0f) - (y2 ? s2 : 0.0f) + LN2 * __log2f(1.0f + e2);
        acc += fmaxf(s3, 0.0f) - (y3 ? s3 : 0.0f) + LN2 * __log2f(1.0f + e3);
    }

    // Tail edges (n_edges % 4).
    if (gtid == 0) {
        for (int e = nq << 2; e < n_edges; e++) {
            int ia = min(src_idx[e], guard);
            int ib = min(dst_idx[e], guard);
            unsigned a = (s_tbl4[ia >> 1] >> ((ia & 1) << 2)) & 15u;
            unsigned b = (s_tbl4[ib >> 1] >> ((ib & 1) << 2)) & 15u;
            unsigned y = (s_mask[(a << 5) | lane] >> b) & 1u;
            float s = edge_scores[e];
            acc += fmaxf(s, 0.0f) - (y ? s : 0.0f) +
                   LN2 * __log2f(1.0f + __expf(-fabsf(s)));
        }
    }

    // Block reduction: warp shuffle -> shared -> one double atomic per block.
    __shared__ float red[32];
    int wid = tid >> 5;
    #pragma unroll
    for (int off = 16; off > 0; off >>= 1)
        acc += __shfl_xor_sync(0xFFFFFFFFu, acc, off);
    if (lane == 0) red[wid] = acc;
    __syncthreads();
    if (wid == 0) {
        int nw = nthreads >> 5;
        float v = (lane < nw) ? red[lane] : 0.0f;
        #pragma unroll
        for (int off = 16; off > 0; off >>= 1)
            v += __shfl_xor_sync(0xFFFFFFFFu, v, off);
        if (lane == 0) {
            atomicAdd(&g_sum, (double)v);
            __threadfence();
            unsigned done = atomicAdd(&g_count, 1u);
            if (done == gridDim.x - 1) {
                double total = *((volatile double*)&g_sum);
                out[0] = (float)(total / (double)n_edges);
            }
        }
    }
}

extern "C" void kernel_launch(void* const* d_in, const int* in_sizes, int n_in,
                              void* d_out, int out_size) {
    // Inputs: node_classes(int32), edge_scores(f32), edge_indices(int32, 2xN),
    // valid_adjacency(f32, CxC).
    const int* node_classes = (const int*)d_in[0];
    const float* edge_scores = (const float*)d_in[1];
    const int* edge_indices = (const int*)d_in[2];
    const float* adj = (const float*)d_in[3];

    int n_nodes = in_sizes[0];
    int n_edges = in_sizes[1];
    int C = 1;
    while (C * C < in_sizes[3]) C++;  // 144 -> 12

    int tbl_bytes = (n_nodes + 1) >> 1;
    int mask_off = (tbl_bytes + 127) & ~127;
    size_t smem_bytes = (size_t)mask_off + (size_t)C * 32 * sizeof(unsigned int);

    cudaFuncSetAttribute(edge_loss_kernel,
                         cudaFuncAttributeMaxDynamicSharedMemorySize,
                         (int)smem_bytes);

    int nsm = 148;
    cudaDeviceGetAttribute(&nsm, cudaDevAttrMultiProcessorCount, 0);

    int pack_threads = 256;
    int pack_blocks = (((n_nodes + 1) / 2) + pack_threads - 1) / pack_threads;
    pack_kernel<<<pack_blocks, pack_threads>>>(node_classes, n_nodes);

    // 2 CTAs per SM (smem ~51KB each), 768 threads -> 48 warps/SM.
    edge_loss_kernel<<<2 * nsm, 768, smem_bytes>>>(edge_scores, edge_indices,
                                                   adj, (float*)d_out,
                                                   n_edges, n_nodes, C);
}